// round 12
// baseline (speedup 1.0000x reference)
#include <cuda_runtime.h>
#include <stdint.h>

#define BATCH 16
#define NPTS  131072
#define NSAMP 1024
#define BPB   8                      // blocks per batch
#define PTS   (NPTS / BPB)           // 16384 points per block
#define TH    512                    // threads per block
#define NW    (TH / 32)              // 16 warps
#define KK    (PTS / (4 * TH))       // 8 x 4-point chunks per thread
#define SMEM_BYTES (PTS * 3 * (int)sizeof(float))   // 196608

#define OFF_SCALE (BATCH * NSAMP * 3)   // 49152
#define OFF_IDX   (OFF_SCALE + BATCH)   // 49168

typedef unsigned long long u64;
typedef unsigned int       u32;

// per-batch exchange: one 8B slot per CTA per parity (4 parities).
// key nonzero by construction (~idx >= 0xFFFE0000) -> nonzero means arrived.
struct __align__(256) Exch { u64 slot[4][BPB]; };

__device__ Exch  g_ex[BATCH];
__device__ int   g_idx[BATCH * NSAMP];
__device__ float g_scale[BATCH];
__device__ float g_psum[BATCH][BPB][3];
__device__ float g_pmax[BATCH][BPB];

// ---------------------------------------------------------------------------
// helpers
// ---------------------------------------------------------------------------
__device__ __forceinline__ u64 add2(u64 a, u64 b) {
    u64 d; asm("add.rn.f32x2 %0,%1,%2;" : "=l"(d) : "l"(a), "l"(b)); return d;
}
__device__ __forceinline__ u64 mul2(u64 a, u64 b) {
    u64 d; asm("mul.rn.f32x2 %0,%1,%2;" : "=l"(d) : "l"(a), "l"(b)); return d;
}
__device__ __forceinline__ void unpack2(u64 v, int& lo, int& hi) {
    asm("mov.b64 {%0,%1},%2;" : "=r"(lo), "=r"(hi) : "l"(v));
}
__device__ __forceinline__ u64 bcast2(float v) {
    u32 b = __float_as_uint(v); return ((u64)b << 32) | (u64)b;
}
__device__ __forceinline__ u64 ld_acq64(const u64* p) {
    u64 v; asm volatile("ld.acquire.gpu.global.u64 %0,[%1];" : "=l"(v) : "l"(p) : "memory");
    return v;
}
__device__ __forceinline__ void st_zero64(u64* p) {
    asm volatile("st.relaxed.gpu.global.u64 [%0],0;" :: "l"(p) : "memory");
}
__device__ __forceinline__ void st_rel64(u64* p, u64 v) {
    asm volatile("st.release.gpu.global.u64 [%0],%1;" :: "l"(p), "l"(v) : "memory");
}

// ---------------------------------------------------------------------------
// Scale pass 1: per-slice partial sums (deterministic tree)
// ---------------------------------------------------------------------------
__global__ void __launch_bounds__(512, 1)
scale1_kernel(const float* __restrict__ mesh)
{
    const int b = blockIdx.x / BPB, s = blockIdx.x % BPB, tid = threadIdx.x;
    const float* base = mesh + (size_t)b * NPTS * 3 + (size_t)s * PTS * 3;

    float sx = 0.f, sy = 0.f, sz = 0.f;
    for (int p = tid; p < PTS; p += 512) {
        const float* q = base + (size_t)p * 3;
        sx += q[0]; sy += q[1]; sz += q[2];
    }
    __shared__ float red[3][16];
    #pragma unroll
    for (int off = 16; off; off >>= 1) {
        sx += __shfl_xor_sync(0xffffffffu, sx, off);
        sy += __shfl_xor_sync(0xffffffffu, sy, off);
        sz += __shfl_xor_sync(0xffffffffu, sz, off);
    }
    const int w = tid >> 5, l = tid & 31;
    if (l == 0) { red[0][w] = sx; red[1][w] = sy; red[2][w] = sz; }
    __syncthreads();
    if (w == 0 && l < 16) {
        sx = red[0][l]; sy = red[1][l]; sz = red[2][l];
        #pragma unroll
        for (int off = 8; off; off >>= 1) {
            sx += __shfl_xor_sync(0xffffffffu, sx, off);
            sy += __shfl_xor_sync(0xffffffffu, sy, off);
            sz += __shfl_xor_sync(0xffffffffu, sz, off);
        }
        if (l == 0) {
            g_psum[b][s][0] = sx; g_psum[b][s][1] = sy; g_psum[b][s][2] = sz;
        }
    }
}

// ---------------------------------------------------------------------------
// Scale pass 2: finalize mean (fixed order), partial max of dist^2 per slice
// ---------------------------------------------------------------------------
__global__ void __launch_bounds__(512, 1)
scale2_kernel(const float* __restrict__ mesh)
{
    const int b = blockIdx.x / BPB, s = blockIdx.x % BPB, tid = threadIdx.x;

    float mx = 0.f, my = 0.f, mz = 0.f;
    #pragma unroll
    for (int i = 0; i < BPB; i++) {
        mx += g_psum[b][i][0]; my += g_psum[b][i][1]; mz += g_psum[b][i][2];
    }
    const float cx = mx * (1.0f / NPTS), cy = my * (1.0f / NPTS), cz = mz * (1.0f / NPTS);

    const float* base = mesh + (size_t)b * NPTS * 3 + (size_t)s * PTS * 3;
    float m = 0.f;
    for (int p = tid; p < PTS; p += 512) {
        const float* q = base + (size_t)p * 3;
        float dx = q[0] - cx, dy = q[1] - cy, dz = q[2] - cz;
        m = fmaxf(m, dx * dx + dy * dy + dz * dz);
    }
    __shared__ float red[16];
    #pragma unroll
    for (int off = 16; off; off >>= 1)
        m = fmaxf(m, __shfl_xor_sync(0xffffffffu, m, off));
    const int w = tid >> 5, l = tid & 31;
    if (l == 0) red[w] = m;
    __syncthreads();
    if (w == 0 && l < 16) {
        m = red[l];
        #pragma unroll
        for (int off = 8; off; off >>= 1)
            m = fmaxf(m, __shfl_xor_sync(0xffffffffu, m, off));
        if (l == 0) g_pmax[b][s] = m;
    }
}

// ---------------------------------------------------------------------------
// Scale pass 3: final max -> sqrt, write scale, reset exchange slots
// ---------------------------------------------------------------------------
__global__ void scale3_kernel(float* __restrict__ out)
{
    const int b = blockIdx.x, l = threadIdx.x;
    float m = (l < BPB) ? g_pmax[b][l] : 0.f;
    #pragma unroll
    for (int off = 4; off; off >>= 1)
        m = fmaxf(m, __shfl_xor_sync(0xffffffffu, m, off));
    if (l < 32) {                        // zero all 4*BPB slots (graph replays)
        u64* base = &g_ex[b].slot[0][0];
        if (l < 4 * BPB) base[l] = 0;
    }
    if (l == 0) {
        float sc = __fsqrt_rn(m);        // sqrt(max) == max(sqrt): monotone
        g_scale[b] = sc;
        out[OFF_SCALE + b] = sc;
    }
}

// ---------------------------------------------------------------------------
// FPS: 8 CTAs per batch. Exchange = slot-per-CTA release stores (no atomics):
//   publisher warp (elected via smem arrival count) stores its CTA key,
//   polls all 8 slots with ONE coalesced 8-lane acquire load per round,
//   shfl-merges the keys it already holds, LDGs winner coords, smem-bcasts.
// One __syncthreads per iteration.
// ---------------------------------------------------------------------------
__global__ void __launch_bounds__(TH, 1)
fps_kernel(const float* __restrict__ mesh, const int* __restrict__ finit)
{
    extern __shared__ float sm[];
    float* sx = sm;
    float* sy = sm + PTS;
    float* sz = sm + 2 * PTS;

    const int blk = blockIdx.x;
    const int b = blk / BPB;
    const int s = blk - b * BPB;
    const int tid = threadIdx.x;
    const int l = tid & 31;

    const float* mb = mesh + (size_t)b * NPTS * 3;
    Exch* E = &g_ex[b];

    __shared__ u64   skey_sm[2];      // per-parity CTA-winner accumulator
    __shared__ u32   scnt_sm[2];      // per-parity warp arrival count
    __shared__ float sbc[4];          // winner broadcast: x, y, z, idx_bits

    if (tid == 0) {
        skey_sm[0] = 0; skey_sm[1] = 0;
        scnt_sm[0] = 0; scnt_sm[1] = 0;
    }

    // stage this block's xyz slice into SMEM (SoA, one-time)
    {
        const float* gsrc = mb + (size_t)s * PTS * 3;
        for (int e = tid; e < PTS * 3; e += TH) {
            float v = gsrc[e];
            int p = e / 3;
            int c = e - 3 * p;
            sm[c * PTS + p] = v;
        }
    }

    // per-thread min-distances as int bit patterns (all values >= 0)
    int di[4 * KK];
    #pragma unroll
    for (int k = 0; k < 4 * KK; k++) di[k] = __float_as_int(1e10f);

    int fidx = finit[b];
    float cx = mb[(size_t)fidx * 3 + 0];
    float cy = mb[(size_t)fidx * 3 + 1];
    float cz = mb[(size_t)fidx * 3 + 2];

    __syncthreads();

    const ulonglong2* sxp = (const ulonglong2*)sx;
    const ulonglong2* syp = (const ulonglong2*)sy;
    const ulonglong2* szp = (const ulonglong2*)sz;

    for (int t = 0; t < NSAMP; ++t) {
        if (s == 0 && tid == 0) g_idx[b * NSAMP + t] = fidx;   // record BEFORE update
        if (t == NSAMP - 1) break;

        const u64 ncx = bcast2(-cx), ncy = bcast2(-cy), ncz = bcast2(-cz);

        int bvi = -1;            // int compare == float compare for nonneg floats
        int bp  = 0x7fffffff;

        #pragma unroll
        for (int k = 0; k < KK; k++) {
            const int c = k * TH + tid;
            ulonglong2 X = sxp[c];
            ulonglong2 Y = syp[c];
            ulonglong2 Z = szp[c];
            const int base = s * PTS + 4 * c;
            {   // points base, base+1
                u64 dx = add2(X.x, ncx), dy = add2(Y.x, ncy), dz = add2(Z.x, ncz);
                u64 d2 = add2(add2(mul2(dx, dx), mul2(dy, dy)), mul2(dz, dz));
                int a0, a1; unpack2(d2, a0, a1);
                int n0 = min(a0, di[4 * k + 0]); di[4 * k + 0] = n0;
                int n1 = min(a1, di[4 * k + 1]); di[4 * k + 1] = n1;
                if (n0 > bvi) { bvi = n0; bp = base; }
                if (n1 > bvi) { bvi = n1; bp = base + 1; }
            }
            {   // points base+2, base+3
                u64 dx = add2(X.y, ncx), dy = add2(Y.y, ncy), dz = add2(Z.y, ncz);
                u64 d2 = add2(add2(mul2(dx, dx), mul2(dy, dy)), mul2(dz, dz));
                int a0, a1; unpack2(d2, a0, a1);
                int n0 = min(a0, di[4 * k + 2]); di[4 * k + 2] = n0;
                int n1 = min(a1, di[4 * k + 3]); di[4 * k + 3] = n1;
                if (n0 > bvi) { bvi = n0; bp = base + 2; }
                if (n1 > bvi) { bvi = n1; bp = base + 3; }
            }
        }

        // packed key: dist desc, index asc on ties -> single u64 max; nonzero.
        u64 key = ((u64)(u32)bvi << 32) | (u32)(~bp);
        #pragma unroll
        for (int off = 16; off; off >>= 1) {
            u64 ok = __shfl_down_sync(0xffffffffu, key, off);
            if (ok > key) key = ok;
        }

        const int sp = t & 1;             // smem slot parity
        const int par = t & 3;            // L2 slot parity
        int old = 0;
        if (l == 0) {
            atomicMax_block(&skey_sm[sp], key);
            __threadfence_block();        // order max before arrival count
            old = (int)atomicAdd_block(&scnt_sm[sp], 1u);
        }
        old = __shfl_sync(0xffffffffu, old, 0);

        if (old == NW - 1) {              // last-arriving warp = publisher
            __threadfence_block();
            u64 ck = *(volatile u64*)&skey_sm[sp];      // CTA winner
            if (l == 0) {
                st_zero64(&E->slot[(t + 1) & 3][s]);    // recycle own next slot
                st_rel64(&E->slot[par][s], ck);         // publish (release)
            }
            if (l == 1) skey_sm[sp] = 0;  // reset smem slot for iter t+2
            if (l == 2) scnt_sm[sp] = 0;

            // poll: one coalesced 8-lane acquire load per round
            u64 v = 0; u32 ball;
            do {
                if (l < BPB) v = ld_acq64(&E->slot[par][l]);
                ball = __ballot_sync(0xffffffffu, v != 0ull);
            } while ((ball & 0xffu) != 0xffu);

            // merge the 8 keys already in lanes 0-7
            u64 m = v;
            #pragma unroll
            for (int off = 4; off; off >>= 1) {
                u64 o = __shfl_down_sync(0xffffffffu, m, off, 8);
                if (o > m) m = o;
            }
            m = __shfl_sync(0xffffffffu, m, 0);
            const int widx = (int)(~(u32)m);
            const float* q = mb + (size_t)widx * 3;
            if (l < 3) sbc[l] = __ldg(q + l);           // 3 parallel coord loads
            if (l == 3) sbc[3] = __int_as_float(widx);
        }
        __syncthreads();                  // the ONLY block barrier per iteration

        cx = sbc[0]; cy = sbc[1]; cz = sbc[2];
        fidx = __float_as_int(sbc[3]);
    }
}

// ---------------------------------------------------------------------------
// Gather: sample points, normalize, emit idx as float
// ---------------------------------------------------------------------------
__global__ void __launch_bounds__(1024, 1)
gather_kernel(const float* __restrict__ mesh, float* __restrict__ out)
{
    const int b = blockIdx.x;
    const int j = threadIdx.x;
    const int i = g_idx[b * NSAMP + j];
    const float sc = g_scale[b];
    const float* q = mesh + ((size_t)b * NPTS + (size_t)i) * 3;
    const size_t o = ((size_t)b * NSAMP + j) * 3;
    out[o + 0] = __fdiv_rn(q[0], sc);
    out[o + 1] = __fdiv_rn(q[1], sc);
    out[o + 2] = __fdiv_rn(q[2], sc);
    out[OFF_IDX + b * NSAMP + j] = (float)i;   // exact: i < 2^24
}

// ---------------------------------------------------------------------------
extern "C" void kernel_launch(void* const* d_in, const int* in_sizes, int n_in,
                              void* d_out, int out_size)
{
    const float* mesh  = (const float*)d_in[0];
    const int*   finit = (const int*)d_in[1];
    float* out = (float*)d_out;

    cudaFuncSetAttribute(fps_kernel,
                         cudaFuncAttributeMaxDynamicSharedMemorySize, SMEM_BYTES);

    scale1_kernel<<<BATCH * BPB, 512>>>(mesh);
    scale2_kernel<<<BATCH * BPB, 512>>>(mesh);
    scale3_kernel<<<BATCH, 32>>>(out);                         // also resets g_ex
    fps_kernel<<<BATCH * BPB, TH, SMEM_BYTES>>>(mesh, finit);  // 128 blocks co-resident
    gather_kernel<<<BATCH, 1024>>>(mesh, out);
}

// round 13
// speedup vs baseline: 1.0466x; 1.0466x over previous
#include <cuda_runtime.h>
#include <stdint.h>

#define BATCH 16
#define NPTS  131072
#define NSAMP 1024
#define BPB   16                     // CTAs per batch (2 batches co-resident/SM)
#define PTS   (NPTS / BPB)           // 8192 points per CTA
#define TH    256                    // threads per CTA
#define NW    (TH / 32)              // 8 warps
#define KK    (PTS / (4 * TH))       // 8 x 4-point chunks per thread
#define SMEM_BYTES (PTS * 3 * (int)sizeof(float))   // 98304

#define OFF_SCALE (BATCH * NSAMP * 3)   // 49152
#define OFF_IDX   (OFF_SCALE + BATCH)   // 49168

typedef unsigned long long u64;
typedef unsigned int       u32;

// per-batch exchange: one 8B slot per CTA per parity; each parity = one 128B
// line. key nonzero by construction (~idx >= 0xFFFC0000) -> nonzero = arrived.
struct __align__(128) Exch { u64 slot[4][BPB]; };

__device__ Exch  g_ex[BATCH];
__device__ int   g_idx[BATCH * NSAMP];
__device__ float g_scale[BATCH];
__device__ float g_psum[BATCH][BPB][3];
__device__ float g_pmax[BATCH][BPB];

// ---------------------------------------------------------------------------
// helpers
// ---------------------------------------------------------------------------
__device__ __forceinline__ u64 add2(u64 a, u64 b) {
    u64 d; asm("add.rn.f32x2 %0,%1,%2;" : "=l"(d) : "l"(a), "l"(b)); return d;
}
__device__ __forceinline__ u64 mul2(u64 a, u64 b) {
    u64 d; asm("mul.rn.f32x2 %0,%1,%2;" : "=l"(d) : "l"(a), "l"(b)); return d;
}
__device__ __forceinline__ void unpack2(u64 v, int& lo, int& hi) {
    asm("mov.b64 {%0,%1},%2;" : "=r"(lo), "=r"(hi) : "l"(v));
}
__device__ __forceinline__ u64 bcast2(float v) {
    u32 b = __float_as_uint(v); return ((u64)b << 32) | (u64)b;
}
__device__ __forceinline__ u64 ld_acq64(const u64* p) {
    u64 v; asm volatile("ld.acquire.gpu.global.u64 %0,[%1];" : "=l"(v) : "l"(p) : "memory");
    return v;
}
__device__ __forceinline__ void st_zero64(u64* p) {
    asm volatile("st.relaxed.gpu.global.u64 [%0],0;" :: "l"(p) : "memory");
}
__device__ __forceinline__ void st_rel64(u64* p, u64 v) {
    asm volatile("st.release.gpu.global.u64 [%0],%1;" :: "l"(p), "l"(v) : "memory");
}

// ---------------------------------------------------------------------------
// Scale pass 1: per-slice partial sums (deterministic tree)
// ---------------------------------------------------------------------------
__global__ void __launch_bounds__(512, 1)
scale1_kernel(const float* __restrict__ mesh)
{
    const int b = blockIdx.x / BPB, s = blockIdx.x % BPB, tid = threadIdx.x;
    const float* base = mesh + (size_t)b * NPTS * 3 + (size_t)s * PTS * 3;

    float sx = 0.f, sy = 0.f, sz = 0.f;
    for (int p = tid; p < PTS; p += 512) {
        const float* q = base + (size_t)p * 3;
        sx += q[0]; sy += q[1]; sz += q[2];
    }
    __shared__ float red[3][16];
    #pragma unroll
    for (int off = 16; off; off >>= 1) {
        sx += __shfl_xor_sync(0xffffffffu, sx, off);
        sy += __shfl_xor_sync(0xffffffffu, sy, off);
        sz += __shfl_xor_sync(0xffffffffu, sz, off);
    }
    const int w = tid >> 5, l = tid & 31;
    if (l == 0) { red[0][w] = sx; red[1][w] = sy; red[2][w] = sz; }
    __syncthreads();
    if (w == 0 && l < 16) {
        sx = red[0][l]; sy = red[1][l]; sz = red[2][l];
        #pragma unroll
        for (int off = 8; off; off >>= 1) {
            sx += __shfl_xor_sync(0xffffffffu, sx, off);
            sy += __shfl_xor_sync(0xffffffffu, sy, off);
            sz += __shfl_xor_sync(0xffffffffu, sz, off);
        }
        if (l == 0) {
            g_psum[b][s][0] = sx; g_psum[b][s][1] = sy; g_psum[b][s][2] = sz;
        }
    }
}

// ---------------------------------------------------------------------------
// Scale pass 2: finalize mean (fixed order), partial max of dist^2 per slice
// ---------------------------------------------------------------------------
__global__ void __launch_bounds__(512, 1)
scale2_kernel(const float* __restrict__ mesh)
{
    const int b = blockIdx.x / BPB, s = blockIdx.x % BPB, tid = threadIdx.x;

    float mx = 0.f, my = 0.f, mz = 0.f;
    #pragma unroll
    for (int i = 0; i < BPB; i++) {
        mx += g_psum[b][i][0]; my += g_psum[b][i][1]; mz += g_psum[b][i][2];
    }
    const float cx = mx * (1.0f / NPTS), cy = my * (1.0f / NPTS), cz = mz * (1.0f / NPTS);

    const float* base = mesh + (size_t)b * NPTS * 3 + (size_t)s * PTS * 3;
    float m = 0.f;
    for (int p = tid; p < PTS; p += 512) {
        const float* q = base + (size_t)p * 3;
        float dx = q[0] - cx, dy = q[1] - cy, dz = q[2] - cz;
        m = fmaxf(m, dx * dx + dy * dy + dz * dz);
    }
    __shared__ float red[16];
    #pragma unroll
    for (int off = 16; off; off >>= 1)
        m = fmaxf(m, __shfl_xor_sync(0xffffffffu, m, off));
    const int w = tid >> 5, l = tid & 31;
    if (l == 0) red[w] = m;
    __syncthreads();
    if (w == 0 && l < 16) {
        m = red[l];
        #pragma unroll
        for (int off = 8; off; off >>= 1)
            m = fmaxf(m, __shfl_xor_sync(0xffffffffu, m, off));
        if (l == 0) g_pmax[b][s] = m;
    }
}

// ---------------------------------------------------------------------------
// Scale pass 3: final max -> sqrt, write scale, reset exchange slots
// ---------------------------------------------------------------------------
__global__ void scale3_kernel(float* __restrict__ out)
{
    const int b = blockIdx.x, tid = threadIdx.x;
    u64* base = &g_ex[b].slot[0][0];
    if (tid < 4 * BPB) base[tid] = 0;    // zero all 64 slots (graph replays)

    if (tid < 32) {
        float m = (tid < BPB) ? g_pmax[b][tid] : 0.f;
        #pragma unroll
        for (int off = 8; off; off >>= 1)
            m = fmaxf(m, __shfl_xor_sync(0xffffffffu, m, off));
        if (tid == 0) {
            float sc = __fsqrt_rn(m);    // sqrt(max) == max(sqrt): monotone
            g_scale[b] = sc;
            out[OFF_SCALE + b] = sc;
        }
    }
}

// ---------------------------------------------------------------------------
// FPS: 16 CTAs/batch, 2 CTAs (different batches) per SM -> one CTA's exchange
// tail overlaps the other's compute. Tail = shfl reduce (no smem atomics) +
// release slot-store + ONE coalesced 16-lane acquire poll + shfl merge.
// ---------------------------------------------------------------------------
__global__ void __launch_bounds__(TH, 2)
fps_kernel(const float* __restrict__ mesh, const int* __restrict__ finit)
{
    extern __shared__ float sm[];
    float* sx = sm;
    float* sy = sm + PTS;
    float* sz = sm + 2 * PTS;

    const int blk = blockIdx.x;
    const int b = blk / BPB;
    const int s = blk - b * BPB;
    const int tid = threadIdx.x;
    const int w = tid >> 5, l = tid & 31;

    const float* mb = mesh + (size_t)b * NPTS * 3;
    Exch* E = &g_ex[b];

    __shared__ u64   skey[NW];
    __shared__ float sbc[4];          // winner broadcast: x, y, z, idx_bits

    // stage this CTA's xyz slice into SMEM (SoA, one-time)
    {
        const float* gsrc = mb + (size_t)s * PTS * 3;
        for (int e = tid; e < PTS * 3; e += TH) {
            float v = gsrc[e];
            int p = e / 3;
            int c = e - 3 * p;
            sm[c * PTS + p] = v;
        }
    }

    // per-thread min-distances as int bit patterns (all values >= 0)
    int di[4 * KK];
    #pragma unroll
    for (int k = 0; k < 4 * KK; k++) di[k] = __float_as_int(1e10f);

    int fidx = finit[b];
    float cx = mb[(size_t)fidx * 3 + 0];
    float cy = mb[(size_t)fidx * 3 + 1];
    float cz = mb[(size_t)fidx * 3 + 2];

    __syncthreads();

    const ulonglong2* sxp = (const ulonglong2*)sx;
    const ulonglong2* syp = (const ulonglong2*)sy;
    const ulonglong2* szp = (const ulonglong2*)sz;

    for (int t = 0; t < NSAMP; ++t) {
        if (s == 0 && tid == 0) g_idx[b * NSAMP + t] = fidx;   // record BEFORE update
        if (t == NSAMP - 1) break;

        const u64 ncx = bcast2(-cx), ncy = bcast2(-cy), ncz = bcast2(-cz);

        int bvi = -1;            // int compare == float compare for nonneg floats
        int bp  = 0x7fffffff;

        #pragma unroll
        for (int k = 0; k < KK; k++) {
            const int c = k * TH + tid;
            ulonglong2 X = sxp[c];
            ulonglong2 Y = syp[c];
            ulonglong2 Z = szp[c];
            const int base = s * PTS + 4 * c;
            {   // points base, base+1
                u64 dx = add2(X.x, ncx), dy = add2(Y.x, ncy), dz = add2(Z.x, ncz);
                u64 d2 = add2(add2(mul2(dx, dx), mul2(dy, dy)), mul2(dz, dz));
                int a0, a1; unpack2(d2, a0, a1);
                int n0 = min(a0, di[4 * k + 0]); di[4 * k + 0] = n0;
                int n1 = min(a1, di[4 * k + 1]); di[4 * k + 1] = n1;
                if (n0 > bvi) { bvi = n0; bp = base; }
                if (n1 > bvi) { bvi = n1; bp = base + 1; }
            }
            {   // points base+2, base+3
                u64 dx = add2(X.y, ncx), dy = add2(Y.y, ncy), dz = add2(Z.y, ncz);
                u64 d2 = add2(add2(mul2(dx, dx), mul2(dy, dy)), mul2(dz, dz));
                int a0, a1; unpack2(d2, a0, a1);
                int n0 = min(a0, di[4 * k + 2]); di[4 * k + 2] = n0;
                int n1 = min(a1, di[4 * k + 3]); di[4 * k + 3] = n1;
                if (n0 > bvi) { bvi = n0; bp = base + 2; }
                if (n1 > bvi) { bvi = n1; bp = base + 3; }
            }
        }

        // packed key: dist desc, index asc on ties -> single u64 max; nonzero.
        u64 key = ((u64)(u32)bvi << 32) | (u32)(~bp);
        #pragma unroll
        for (int off = 16; off; off >>= 1) {
            u64 ok = __shfl_down_sync(0xffffffffu, key, off);
            if (ok > key) key = ok;
        }
        if (l == 0) skey[w] = key;
        __syncthreads();

        const int par = t & 3;
        if (w == 0) {
            // level-2 reduce over 8 warp keys (pure shfl, no atomics)
            key = (l < NW) ? skey[l] : 0ull;
            #pragma unroll
            for (int off = NW / 2; off; off >>= 1) {
                u64 ok = __shfl_down_sync(0xffffffffu, key, off);
                if (ok > key) key = ok;
            }
            if (l == 0) {
                st_zero64(&E->slot[(t + 1) & 3][s]);    // recycle own next slot
                st_rel64(&E->slot[par][s], key);        // publish (release)
            }

            // poll: one coalesced 16-lane acquire load per round
            u64 v = 0; u32 ball;
            do {
                if (l < BPB) v = ld_acq64(&E->slot[par][l]);
                ball = __ballot_sync(0xffffffffu, v != 0ull);
            } while ((ball & 0xffffu) != 0xffffu);

            // merge the 16 keys already in lanes 0-15
            u64 m = v;
            #pragma unroll
            for (int off = 8; off; off >>= 1) {
                u64 o = __shfl_down_sync(0xffffffffu, m, off, 16);
                if (o > m) m = o;
            }
            m = __shfl_sync(0xffffffffu, m, 0);
            const int widx = (int)(~(u32)m);
            const float* q = mb + (size_t)widx * 3;
            if (l < 3) sbc[l] = __ldg(q + l);           // 3 parallel coord loads
            if (l == 3) sbc[3] = __int_as_float(widx);
        }
        __syncthreads();                  // the ONLY other block barrier

        cx = sbc[0]; cy = sbc[1]; cz = sbc[2];
        fidx = __float_as_int(sbc[3]);
    }
}

// ---------------------------------------------------------------------------
// Gather: sample points, normalize, emit idx as float
// ---------------------------------------------------------------------------
__global__ void __launch_bounds__(1024, 1)
gather_kernel(const float* __restrict__ mesh, float* __restrict__ out)
{
    const int b = blockIdx.x;
    const int j = threadIdx.x;
    const int i = g_idx[b * NSAMP + j];
    const float sc = g_scale[b];
    const float* q = mesh + ((size_t)b * NPTS + (size_t)i) * 3;
    const size_t o = ((size_t)b * NSAMP + j) * 3;
    out[o + 0] = __fdiv_rn(q[0], sc);
    out[o + 1] = __fdiv_rn(q[1], sc);
    out[o + 2] = __fdiv_rn(q[2], sc);
    out[OFF_IDX + b * NSAMP + j] = (float)i;   // exact: i < 2^24
}

// ---------------------------------------------------------------------------
extern "C" void kernel_launch(void* const* d_in, const int* in_sizes, int n_in,
                              void* d_out, int out_size)
{
    const float* mesh  = (const float*)d_in[0];
    const int*   finit = (const int*)d_in[1];
    float* out = (float*)d_out;

    cudaFuncSetAttribute(fps_kernel,
                         cudaFuncAttributeMaxDynamicSharedMemorySize, SMEM_BYTES);

    scale1_kernel<<<BATCH * BPB, 512>>>(mesh);
    scale2_kernel<<<BATCH * BPB, 512>>>(mesh);
    scale3_kernel<<<BATCH, 64>>>(out);                         // also resets g_ex
    fps_kernel<<<BATCH * BPB, TH, SMEM_BYTES>>>(mesh, finit);  // 256 CTAs, 2/SM
    gather_kernel<<<BATCH, 1024>>>(mesh, out);
}

// round 14
// speedup vs baseline: 1.5066x; 1.4395x over previous
#include <cuda_runtime.h>
#include <stdint.h>

#define BATCH 16
#define NPTS  131072
#define NSAMP 1024
#define BPB   8                      // blocks per batch
#define PTS   (NPTS / BPB)           // 16384 points per block
#define TH    512                    // threads per block
#define NW    (TH / 32)              // 16 warps
#define KK    (PTS / (4 * TH))       // 8 x 4-point chunks per thread
#define SMEM_BYTES (PTS * 3 * (int)sizeof(float))   // 196608

#define OFF_SCALE (BATCH * NSAMP * 3)   // 49152
#define OFF_IDX   (OFF_SCALE + BATCH)   // 49168

typedef unsigned long long u64;
typedef unsigned int       u32;

// per-batch exchange: 4 parities x 8 CTA-slots x 32B (two float4 halves).
// half0 = {key_lo=(seq<<17)|idxfield, key_hi=distbits, x, y}, half1 = {z, seq}.
// Each 16B half is one STG.128/LDG.128 -> atomic; seq validates freshness.
struct __align__(256) Exch { float4 slot[4][BPB][2]; };

__device__ Exch  g_ex[BATCH];
__device__ int   g_idx[BATCH * NSAMP];
__device__ float g_scale[BATCH];
__device__ float g_psum[BATCH][BPB][3];
__device__ float g_pmax[BATCH][BPB];

// ---------------------------------------------------------------------------
// helpers
// ---------------------------------------------------------------------------
__device__ __forceinline__ u64 add2(u64 a, u64 b) {
    u64 d; asm("add.rn.f32x2 %0,%1,%2;" : "=l"(d) : "l"(a), "l"(b)); return d;
}
__device__ __forceinline__ u64 mul2(u64 a, u64 b) {
    u64 d; asm("mul.rn.f32x2 %0,%1,%2;" : "=l"(d) : "l"(a), "l"(b)); return d;
}
__device__ __forceinline__ void unpack2(u64 v, int& lo, int& hi) {
    asm("mov.b64 {%0,%1},%2;" : "=r"(lo), "=r"(hi) : "l"(v));
}
__device__ __forceinline__ u64 bcast2(float v) {
    u32 b = __float_as_uint(v); return ((u64)b << 32) | (u64)b;
}
__device__ __forceinline__ float4 ldv4_vol(const float4* p) {
    float4 v;
    asm volatile("ld.volatile.global.v4.f32 {%0,%1,%2,%3},[%4];"
                 : "=f"(v.x), "=f"(v.y), "=f"(v.z), "=f"(v.w) : "l"(p) : "memory");
    return v;
}
__device__ __forceinline__ void stv4_vol(float4* p, float4 v) {
    asm volatile("st.volatile.global.v4.f32 [%0],{%1,%2,%3,%4};"
                 :: "l"(p), "f"(v.x), "f"(v.y), "f"(v.z), "f"(v.w) : "memory");
}

// ---------------------------------------------------------------------------
// Scale pass 1: per-slice partial sums (deterministic tree)
// ---------------------------------------------------------------------------
__global__ void __launch_bounds__(512, 1)
scale1_kernel(const float* __restrict__ mesh)
{
    const int b = blockIdx.x / BPB, s = blockIdx.x % BPB, tid = threadIdx.x;
    const float* base = mesh + (size_t)b * NPTS * 3 + (size_t)s * PTS * 3;

    float sx = 0.f, sy = 0.f, sz = 0.f;
    for (int p = tid; p < PTS; p += 512) {
        const float* q = base + (size_t)p * 3;
        sx += q[0]; sy += q[1]; sz += q[2];
    }
    __shared__ float red[3][16];
    #pragma unroll
    for (int off = 16; off; off >>= 1) {
        sx += __shfl_xor_sync(0xffffffffu, sx, off);
        sy += __shfl_xor_sync(0xffffffffu, sy, off);
        sz += __shfl_xor_sync(0xffffffffu, sz, off);
    }
    const int w = tid >> 5, l = tid & 31;
    if (l == 0) { red[0][w] = sx; red[1][w] = sy; red[2][w] = sz; }
    __syncthreads();
    if (w == 0 && l < 16) {
        sx = red[0][l]; sy = red[1][l]; sz = red[2][l];
        #pragma unroll
        for (int off = 8; off; off >>= 1) {
            sx += __shfl_xor_sync(0xffffffffu, sx, off);
            sy += __shfl_xor_sync(0xffffffffu, sy, off);
            sz += __shfl_xor_sync(0xffffffffu, sz, off);
        }
        if (l == 0) {
            g_psum[b][s][0] = sx; g_psum[b][s][1] = sy; g_psum[b][s][2] = sz;
        }
    }
}

// ---------------------------------------------------------------------------
// Scale pass 2: finalize mean (fixed order), partial max of dist^2 per slice
// ---------------------------------------------------------------------------
__global__ void __launch_bounds__(512, 1)
scale2_kernel(const float* __restrict__ mesh)
{
    const int b = blockIdx.x / BPB, s = blockIdx.x % BPB, tid = threadIdx.x;

    float mx = 0.f, my = 0.f, mz = 0.f;
    #pragma unroll
    for (int i = 0; i < BPB; i++) {
        mx += g_psum[b][i][0]; my += g_psum[b][i][1]; mz += g_psum[b][i][2];
    }
    const float cx = mx * (1.0f / NPTS), cy = my * (1.0f / NPTS), cz = mz * (1.0f / NPTS);

    const float* base = mesh + (size_t)b * NPTS * 3 + (size_t)s * PTS * 3;
    float m = 0.f;
    for (int p = tid; p < PTS; p += 512) {
        const float* q = base + (size_t)p * 3;
        float dx = q[0] - cx, dy = q[1] - cy, dz = q[2] - cz;
        m = fmaxf(m, dx * dx + dy * dy + dz * dz);
    }
    __shared__ float red[16];
    #pragma unroll
    for (int off = 16; off; off >>= 1)
        m = fmaxf(m, __shfl_xor_sync(0xffffffffu, m, off));
    const int w = tid >> 5, l = tid & 31;
    if (l == 0) red[w] = m;
    __syncthreads();
    if (w == 0 && l < 16) {
        m = red[l];
        #pragma unroll
        for (int off = 8; off; off >>= 1)
            m = fmaxf(m, __shfl_xor_sync(0xffffffffu, m, off));
        if (l == 0) g_pmax[b][s] = m;
    }
}

// ---------------------------------------------------------------------------
// Scale pass 3: final max -> sqrt, write scale, reset exchange slots
// ---------------------------------------------------------------------------
__global__ void scale3_kernel(float* __restrict__ out)
{
    const int b = blockIdx.x, tid = threadIdx.x;
    float4* base = &g_ex[b].slot[0][0][0];
    if (tid < 4 * BPB * 2) base[tid] = make_float4(0.f, 0.f, 0.f, 0.f);

    if (tid < 32) {
        float m = (tid < BPB) ? g_pmax[b][tid] : 0.f;
        #pragma unroll
        for (int off = 4; off; off >>= 1)
            m = fmaxf(m, __shfl_xor_sync(0xffffffffu, m, off));
        if (tid == 0) {
            float sc = __fsqrt_rn(m);    // sqrt(max) == max(sqrt): monotone
            g_scale[b] = sc;
            out[OFF_SCALE + b] = sc;
        }
    }
}

// ---------------------------------------------------------------------------
// FPS: 8 CTAs per batch. Tail = 2 L2 trips: publish (self-validating 32B
// slot, two atomic STG.128) -> one coalesced 16-lane volatile poll that
// returns keys AND coords -> in-warp merge. No atomics, no fences, no
// separate winner/coords loads.
// ---------------------------------------------------------------------------
__global__ void __launch_bounds__(TH, 1)
fps_kernel(const float* __restrict__ mesh, const int* __restrict__ finit)
{
    extern __shared__ float sm[];
    float* sx = sm;
    float* sy = sm + PTS;
    float* sz = sm + 2 * PTS;

    const int blk = blockIdx.x;
    const int b = blk / BPB;
    const int s = blk - b * BPB;
    const int tid = threadIdx.x;
    const int w = tid >> 5, l = tid & 31;

    const float* mb = mesh + (size_t)b * NPTS * 3;
    Exch* E = &g_ex[b];

    __shared__ u64   skey[NW];
    __shared__ float sbc[4];          // winner broadcast: x, y, z, idx_bits

    // stage this CTA's xyz slice into SMEM (SoA, one-time)
    {
        const float* gsrc = mb + (size_t)s * PTS * 3;
        for (int e = tid; e < PTS * 3; e += TH) {
            float v = gsrc[e];
            int p = e / 3;
            int c = e - 3 * p;
            sm[c * PTS + p] = v;
        }
    }

    // per-thread min-distances as int bit patterns (all values >= 0)
    int di[4 * KK];
    #pragma unroll
    for (int k = 0; k < 4 * KK; k++) di[k] = __float_as_int(1e10f);

    int fidx = finit[b];
    float cx = mb[(size_t)fidx * 3 + 0];
    float cy = mb[(size_t)fidx * 3 + 1];
    float cz = mb[(size_t)fidx * 3 + 2];

    __syncthreads();

    const ulonglong2* sxp = (const ulonglong2*)sx;
    const ulonglong2* syp = (const ulonglong2*)sy;
    const ulonglong2* szp = (const ulonglong2*)sz;

    for (int t = 0; t < NSAMP; ++t) {
        if (s == 0 && tid == 0) g_idx[b * NSAMP + t] = fidx;   // record BEFORE update
        if (t == NSAMP - 1) break;

        const u64 ncx = bcast2(-cx), ncy = bcast2(-cy), ncz = bcast2(-cz);

        int bvi = -1;            // int compare == float compare for nonneg floats
        int bp  = 0x7fffffff;

        #pragma unroll
        for (int k = 0; k < KK; k++) {
            const int c = k * TH + tid;
            ulonglong2 X = sxp[c];
            ulonglong2 Y = syp[c];
            ulonglong2 Z = szp[c];
            const int base = s * PTS + 4 * c;
            {   // points base, base+1
                u64 dx = add2(X.x, ncx), dy = add2(Y.x, ncy), dz = add2(Z.x, ncz);
                u64 d2 = add2(add2(mul2(dx, dx), mul2(dy, dy)), mul2(dz, dz));
                int a0, a1; unpack2(d2, a0, a1);
                int n0 = min(a0, di[4 * k + 0]); di[4 * k + 0] = n0;
                int n1 = min(a1, di[4 * k + 1]); di[4 * k + 1] = n1;
                if (n0 > bvi) { bvi = n0; bp = base; }
                if (n1 > bvi) { bvi = n1; bp = base + 1; }
            }
            {   // points base+2, base+3
                u64 dx = add2(X.y, ncx), dy = add2(Y.y, ncy), dz = add2(Z.y, ncz);
                u64 d2 = add2(add2(mul2(dx, dx), mul2(dy, dy)), mul2(dz, dz));
                int a0, a1; unpack2(d2, a0, a1);
                int n0 = min(a0, di[4 * k + 2]); di[4 * k + 2] = n0;
                int n1 = min(a1, di[4 * k + 3]); di[4 * k + 3] = n1;
                if (n0 > bvi) { bvi = n0; bp = base + 2; }
                if (n1 > bvi) { bvi = n1; bp = base + 3; }
            }
        }

        // local packed key: dist desc, index asc on ties -> single u64 max
        u64 key = ((u64)(u32)bvi << 32) | (u32)(~bp);
        #pragma unroll
        for (int off = 16; off; off >>= 1) {
            u64 ok = __shfl_down_sync(0xffffffffu, key, off);
            if (ok > key) key = ok;
        }
        if (l == 0) skey[w] = key;
        __syncthreads();

        const int par = t & 3;
        const u32 seqv = (u32)(t + 1);                  // 1..1023, nonzero
        if (w == 0) {
            // level-2 reduce over 16 warp keys (pure shfl)
            key = (l < NW) ? skey[l] : 0ull;
            #pragma unroll
            for (int off = 8; off; off >>= 1) {
                u64 ok = __shfl_down_sync(0xffffffffu, key, off);
                if (ok > key) key = ok;
            }
            if (l == 0) {
                const int gp = (int)(~(u32)key);        // this CTA's winner idx
                const int lp = gp - s * PTS;            // -> own SMEM coords
                const float wx = sx[lp], wy = sy[lp], wz = sz[lp];
                // slot-wire key: seq in bits [17:32) of lo, idxfield in [0:17)
                const u32 lo = (seqv << 17) | ((u32)(~(u32)gp) & 0x1FFFFu);
                const u32 hi = (u32)(key >> 32);
                // zero own next-parity slot (readers reach it only after
                // consuming this publish -> same-address order protects it)
                stv4_vol(&E->slot[(t + 1) & 3][s][0], make_float4(0, 0, 0, 0));
                stv4_vol(&E->slot[(t + 1) & 3][s][1], make_float4(0, 0, 0, 0));
                // publish: two atomic 16B stores, each self-validating
                stv4_vol(&E->slot[par][s][1],
                         make_float4(wz, __uint_as_float(seqv), 0.f, 0.f));
                stv4_vol(&E->slot[par][s][0],
                         make_float4(__uint_as_float(lo), __uint_as_float(hi),
                                     wx, wy));
            }

            // poll: lanes 0-15 each load one 16B half (256B, 2 lines)
            const float4* pbase = &E->slot[par][0][0];
            float4 v; u32 ball;
            do {
                if (l < 2 * BPB) v = ldv4_vol(pbase + l);
                bool ok;
                if (l & 1) ok = (__float_as_uint(v.y) == seqv);              // half1
                else       ok = ((__float_as_uint(v.x) >> 17) == seqv);      // half0
                ball = __ballot_sync(0xffffffffu, ok);
            } while ((ball & 0xffffu) != 0xffffu);

            // gather slot j's data into lane j (j < 8)
            float4 h0;
            h0.x = __shfl_sync(0xffffffffu, v.x, 2 * l);
            h0.y = __shfl_sync(0xffffffffu, v.y, 2 * l);
            h0.z = __shfl_sync(0xffffffffu, v.z, 2 * l);
            h0.w = __shfl_sync(0xffffffffu, v.w, 2 * l);
            float zz = __shfl_sync(0xffffffffu, v.x, 2 * l + 1);
            // compare key: (dist << 32) | lo ; seq bits equal across slots
            u64 mk = ((u64)__float_as_uint(h0.y) << 32) | __float_as_uint(h0.x);
            u64 m = mk;
            #pragma unroll
            for (int off = 4; off; off >>= 1) {
                u64 o = __shfl_down_sync(0xffffffffu, m, off, 8);
                if (o > m) m = o;
            }
            m = __shfl_sync(0xffffffffu, m, 0);
            u32 balw = __ballot_sync(0xffffffffu, mk == m) & 0xffu;
            int src = __ffs((int)balw) - 1;             // keys unique (idx bits)
            float wx = __shfl_sync(0xffffffffu, h0.z, src);
            float wy = __shfl_sync(0xffffffffu, h0.w, src);
            float wz = __shfl_sync(0xffffffffu, zz,  src);
            if (l == 0) {
                const int widx = 0x1FFFF - (int)((u32)m & 0x1FFFFu);
                sbc[0] = wx; sbc[1] = wy; sbc[2] = wz;
                sbc[3] = __int_as_float(widx);
            }
        }
        __syncthreads();

        cx = sbc[0]; cy = sbc[1]; cz = sbc[2];
        fidx = __float_as_int(sbc[3]);
    }
}

// ---------------------------------------------------------------------------
// Gather: sample points, normalize, emit idx as float
// ---------------------------------------------------------------------------
__global__ void __launch_bounds__(1024, 1)
gather_kernel(const float* __restrict__ mesh, float* __restrict__ out)
{
    const int b = blockIdx.x;
    const int j = threadIdx.x;
    const int i = g_idx[b * NSAMP + j];
    const float sc = g_scale[b];
    const float* q = mesh + ((size_t)b * NPTS + (size_t)i) * 3;
    const size_t o = ((size_t)b * NSAMP + j) * 3;
    out[o + 0] = __fdiv_rn(q[0], sc);
    out[o + 1] = __fdiv_rn(q[1], sc);
    out[o + 2] = __fdiv_rn(q[2], sc);
    out[OFF_IDX + b * NSAMP + j] = (float)i;   // exact: i < 2^24
}

// ---------------------------------------------------------------------------
extern "C" void kernel_launch(void* const* d_in, const int* in_sizes, int n_in,
                              void* d_out, int out_size)
{
    const float* mesh  = (const float*)d_in[0];
    const int*   finit = (const int*)d_in[1];
    float* out = (float*)d_out;

    cudaFuncSetAttribute(fps_kernel,
                         cudaFuncAttributeMaxDynamicSharedMemorySize, SMEM_BYTES);

    scale1_kernel<<<BATCH * BPB, 512>>>(mesh);
    scale2_kernel<<<BATCH * BPB, 512>>>(mesh);
    scale3_kernel<<<BATCH, 64>>>(out);                         // also resets g_ex
    fps_kernel<<<BATCH * BPB, TH, SMEM_BYTES>>>(mesh, finit);  // 128 blocks co-resident
    gather_kernel<<<BATCH, 1024>>>(mesh, out);
}